// round 8
// baseline (speedup 1.0000x reference)
#include <cuda_runtime.h>
#include <cuda_bf16.h>
#include <cstdint>

// RBF: out[i][j] = exp(-||x_i - y_j||^2), N=M=8192, D=64, fp32.
// dist2 = xn + yn - 2*dot; dot via bf16 hi/lo split on mma.sync (HMMA).
// Round 8: fine-grained ML/EPI interleave. B fragments register-resident per
// tile; warp processes 4 m-blocks, each = 48 HMMA + immediate epilogue of its
// 16 outputs. No monolithic epilogue phase -> tensor pipe stays fed.

#define NN 8192
#define DD 64
#define TILE 128
#define NSM 148
#define NCTA (2 * NSM)          // 296
#define TOTTILES (64 * 64)      // 4096

// smem layout (dynamic): A resident, B double-buffered
#define AH_OFF 0
#define AL_OFF 16384
#define BH_OFF(buf) (32768 + (buf) * 32768)
#define BL_OFF(buf) (32768 + (buf) * 32768 + 16384)
#define SMEM_DYN_BYTES 98304

#define LOG2E      1.4426950408889634f
#define TWO_LOG2E  2.8853900817779268f

__device__ float g_xn[NN];   // ||x_i||^2 * log2(e)
__device__ float g_yn[NN];   // ||y_j||^2 * log2(e)
__device__ __nv_bfloat16 g_xh[NN * DD];
__device__ __nv_bfloat16 g_xl[NN * DD];
__device__ __nv_bfloat16 g_yh[NN * DD];
__device__ __nv_bfloat16 g_yl[NN * DD];

// ------------------------- helpers -----------------------------------------
__device__ __forceinline__ uint32_t smem_u32(const void* p) {
    uint32_t a;
    asm("{ .reg .u64 t; cvta.to.shared.u64 t, %1; cvt.u32.u64 %0, t; }"
        : "=r"(a) : "l"(p));
    return a;
}

__device__ __forceinline__ void cp_async16(uint32_t saddr, const void* gaddr) {
    asm volatile("cp.async.cg.shared.global [%0], [%1], 16;"
                 :: "r"(saddr), "l"(gaddr) : "memory");
}

__device__ __forceinline__ void mbar_init(uint32_t addr, uint32_t cnt) {
    asm volatile("mbarrier.init.shared.b64 [%0], %1;"
                 :: "r"(addr), "r"(cnt) : "memory");
}

__device__ __forceinline__ void cp_arrive_noinc(uint32_t addr) {
    asm volatile("cp.async.mbarrier.arrive.noinc.shared.b64 [%0];"
                 :: "r"(addr) : "memory");
}

__device__ __forceinline__ void mbar_arrive(uint32_t addr) {
    asm volatile("{ .reg .b64 tk; mbarrier.arrive.shared.b64 tk, [%0]; }"
                 :: "r"(addr) : "memory");
}

__device__ __forceinline__ void mbar_wait(uint32_t addr, uint32_t parity) {
    asm volatile(
        "{\n\t.reg .pred P1;\n\t"
        "WL_%=:\n\t"
        "mbarrier.try_wait.parity.acquire.cta.shared::cta.b64 P1, [%0], %1, 0x989680;\n\t"
        "@P1 bra.uni WD_%=;\n\t"
        "bra.uni WL_%=;\n\t"
        "WD_%=:\n\t}"
        :: "r"(addr), "r"(parity) : "memory");
}

__device__ __forceinline__ void ldsm4(uint32_t addr, uint32_t& r0, uint32_t& r1,
                                      uint32_t& r2, uint32_t& r3) {
    asm volatile("ldmatrix.sync.aligned.m8n8.x4.shared.b16 {%0,%1,%2,%3}, [%4];"
                 : "=r"(r0), "=r"(r1), "=r"(r2), "=r"(r3) : "r"(addr));
}

__device__ __forceinline__ void mma16816(float& c0, float& c1, float& c2, float& c3,
                                         uint32_t a0, uint32_t a1, uint32_t a2,
                                         uint32_t a3, uint32_t b0, uint32_t b1) {
    asm volatile(
        "mma.sync.aligned.m16n8k16.row.col.f32.bf16.bf16.f32 "
        "{%0,%1,%2,%3}, {%4,%5,%6,%7}, {%8,%9}, {%0,%1,%2,%3};"
        : "+f"(c0), "+f"(c1), "+f"(c2), "+f"(c3)
        : "r"(a0), "r"(a1), "r"(a2), "r"(a3), "r"(b0), "r"(b1));
}

__device__ __forceinline__ float ex2f(float v) {
    float r;
    asm("ex2.approx.ftz.f32 %0, %1;" : "=f"(r) : "f"(v));
    return r;
}

__device__ __forceinline__ uint32_t swz(uint32_t base, int row, int chunk) {
    return base + row * 128 + (((unsigned)chunk ^ ((unsigned)row & 7u)) << 4);
}

__device__ __forceinline__ void split2(float v0, float v1,
                                       uint32_t& hp, uint32_t& lp) {
    __nv_bfloat16 h0 = __float2bfloat16(v0);
    __nv_bfloat16 h1 = __float2bfloat16(v1);
    __nv_bfloat16 l0 = __float2bfloat16(v0 - __bfloat162float(h0));
    __nv_bfloat16 l1 = __float2bfloat16(v1 - __bfloat162float(h1));
    __nv_bfloat162 hh(h0, h1), ll(l0, l1);
    hp = *reinterpret_cast<uint32_t*>(&hh);
    lp = *reinterpret_cast<uint32_t*>(&ll);
}

// ---------------------------------------------------------------------------
__global__ void presplit_kernel(const float* __restrict__ x,
                                const float* __restrict__ y) {
    int tid = blockIdx.x * blockDim.x + threadIdx.x;
    int row = tid >> 4;
    int q = tid & 15;

    float4 vx = __ldg(reinterpret_cast<const float4*>(x + (size_t)row * DD) + q);
    float4 vy = __ldg(reinterpret_cast<const float4*>(y + (size_t)row * DD) + q);

    uint32_t h0, l0, h1, l1;
    split2(vx.x, vx.y, h0, l0);
    split2(vx.z, vx.w, h1, l1);
    *reinterpret_cast<uint2*>(&g_xh[(size_t)row * DD + q * 4]) = make_uint2(h0, h1);
    *reinterpret_cast<uint2*>(&g_xl[(size_t)row * DD + q * 4]) = make_uint2(l0, l1);
    split2(vy.x, vy.y, h0, l0);
    split2(vy.z, vy.w, h1, l1);
    *reinterpret_cast<uint2*>(&g_yh[(size_t)row * DD + q * 4]) = make_uint2(h0, h1);
    *reinterpret_cast<uint2*>(&g_yl[(size_t)row * DD + q * 4]) = make_uint2(l0, l1);

    float sx = vx.x * vx.x + vx.y * vx.y + vx.z * vx.z + vx.w * vx.w;
    float sy = vy.x * vy.x + vy.y * vy.y + vy.z * vy.z + vy.w * vy.w;
#pragma unroll
    for (int o = 8; o >= 1; o >>= 1) {
        sx += __shfl_xor_sync(0xffffffffu, sx, o, 16);
        sy += __shfl_xor_sync(0xffffffffu, sy, o, 16);
    }
    if (q == 0) {
        g_xn[row] = sx * LOG2E;
        g_yn[row] = sy * LOG2E;
    }
}

// ---------------------------------------------------------------------------
__device__ __forceinline__ void load_A(uint32_t sbase, int t, int row0) {
    const __nv_bfloat16* sh = g_xh + (size_t)row0 * DD;
    const __nv_bfloat16* sl = g_xl + (size_t)row0 * DD;
#pragma unroll
    for (int it = 0; it < 4; it++) {
        int idx = t + 256 * it;
        int r = idx >> 3;
        int q = idx & 7;
        cp_async16(swz(sbase + AH_OFF, r, q), sh + (size_t)r * DD + q * 8);
        cp_async16(swz(sbase + AL_OFF, r, q), sl + (size_t)r * DD + q * 8);
    }
}

__device__ __forceinline__ void load_B(uint32_t sbase, int buf, int t, int col0) {
    const __nv_bfloat16* sh = g_yh + (size_t)col0 * DD;
    const __nv_bfloat16* sl = g_yl + (size_t)col0 * DD;
    const uint32_t bh = sbase + BH_OFF(buf);
    const uint32_t bl = sbase + BL_OFF(buf);
#pragma unroll
    for (int it = 0; it < 4; it++) {
        int idx = t + 256 * it;
        int r = idx >> 3;
        int q = idx & 7;
        cp_async16(swz(bh, r, q), sh + (size_t)r * DD + q * 8);
        cp_async16(swz(bl, r, q), sl + (size_t)r * DD + q * 8);
    }
}

// ---------------------------------------------------------------------------
// Persistent kernel, 256 threads (8 warps: 2x4), grid = 296 (2/SM).
// ---------------------------------------------------------------------------
__global__ __launch_bounds__(256, 2)
void rbf_mma_kernel(float* __restrict__ out) {
    extern __shared__ __align__(128) char smem_raw[];
    const uint32_t sbase = smem_u32(smem_raw);

    __shared__ __align__(8) uint64_t s_mbar[4];  // fill0, fill1, read0, read1

    const int t    = threadIdx.x;
    const int wid  = t >> 5;
    const int lane = t & 31;
    const int b    = blockIdx.x;

    const uint32_t fill_a0 = smem_u32(&s_mbar[0]);
    const uint32_t fill_a1 = smem_u32(&s_mbar[1]);
    const uint32_t read_a0 = smem_u32(&s_mbar[2]);
    const uint32_t read_a1 = smem_u32(&s_mbar[3]);

    if (t == 0) {
        mbar_init(fill_a0, 256);
        mbar_init(fill_a1, 256);
        mbar_init(read_a0, 256);
        mbar_init(read_a1, 256);
    }
    __syncthreads();

    // static tile schedule: contiguous row-major runs
    const int base  = TOTTILES / NCTA;
    const int rem   = TOTTILES % NCTA;
    const int cnt   = base + (b < rem);
    const int start = (b < rem) ? (base + 1) * b : rem * (base + 1) + base * (b - rem);

    // warp tiling constants
    const int warp_row = wid >> 2;
    const int warp_col = wid & 3;
    const int m_base = warp_row * 64;
    const int n_base = warp_col * 32;
    const int a_row = m_base + (lane & 15);
    const int a_half = lane >> 4;
    const int b_row = n_base + ((lane >> 4) & 1) * 8 + (lane & 7);
    const int b_half = (lane >> 3) & 1;
    const int group = lane >> 2;
    const int tig   = lane & 3;

    // prologue
    load_A(sbase, t, (start >> 6) * TILE);
    load_B(sbase, 0, t, (start & 63) * TILE);
    cp_arrive_noinc(fill_a0);

    for (int s = 0; s < cnt; s++) {
        const int id   = start + s;
        const int ti   = id >> 6;
        const int tj   = id & 63;
        const int row0 = ti * TILE;
        const int col0 = tj * TILE;
        const int buf  = s & 1;
        const uint32_t fill_cur = buf ? fill_a1 : fill_a0;
        const uint32_t fill_nxt = buf ? fill_a0 : fill_a1;
        const uint32_t read_cur = buf ? read_a1 : read_a0;
        const uint32_t read_oth = buf ? read_a0 : read_a1;

        // 1. all warps done reading buf^1 (mainloop s-1)
        if (s > 0) mbar_wait(read_oth, ((s - 1) >> 1) & 1);

        const bool strip_entry = (s == 0) || (((id - 1) >> 6) != ti);

        // 2. deferred A+B load at row-strip change
        if (s > 0 && strip_entry) {
            load_A(sbase, t, row0);
            load_B(sbase, buf, t, col0);
            cp_arrive_noinc(fill_cur);
        }
        // 3. prefetch next B if same row strip
        if (s + 1 < cnt && (((id + 1) >> 6) == ti)) {
            load_B(sbase, buf ^ 1, t, ((id + 1) & 63) * TILE);
            cp_arrive_noinc(fill_nxt);
        }

        // y-norms for this tile (L1/L2-resident)
        float ynv[4][2];
#pragma unroll
        for (int n = 0; n < 4; n++) {
            ynv[n][0] = __ldg(&g_yn[col0 + n_base + 8 * n + 2 * tig]);
            ynv[n][1] = __ldg(&g_yn[col0 + n_base + 8 * n + 2 * tig + 1]);
        }

        // 4. wait B(s) ready
        mbar_wait(fill_cur, (s >> 1) & 1);

        // 5. load ALL B fragments into registers (16 ldsm.x4)
        const uint32_t bhb = sbase + BH_OFF(buf);
        const uint32_t blb = sbase + BL_OFF(buf);
        uint32_t bfh[4][4][2], bfl[4][4][2];
#pragma unroll
        for (int kc = 0; kc < 4; kc++) {
            const int b_chunk = kc * 2 + b_half;
#pragma unroll
            for (int p = 0; p < 2; p++) {
                ldsm4(swz(bhb, b_row + 16 * p, b_chunk),
                      bfh[kc][2 * p][0], bfh[kc][2 * p][1],
                      bfh[kc][2 * p + 1][0], bfh[kc][2 * p + 1][1]);
                ldsm4(swz(blb, b_row + 16 * p, b_chunk),
                      bfl[kc][2 * p][0], bfl[kc][2 * p][1],
                      bfl[kc][2 * p + 1][0], bfl[kc][2 * p + 1][1]);
            }
        }

        // 6. m-blocks: 48 HMMA + immediate epilogue of 16 outputs each
#pragma unroll
        for (int m = 0; m < 4; m++) {
            float acc[4][4];
#pragma unroll
            for (int n = 0; n < 4; n++)
#pragma unroll
                for (int e = 0; e < 4; e++) acc[n][e] = 0.f;

#pragma unroll
            for (int kc = 0; kc < 4; kc++) {
                uint32_t ah[4], al[4];
                const int a_chunk = kc * 2 + a_half;
                ldsm4(swz(sbase + AH_OFF, a_row + 16 * m, a_chunk),
                      ah[0], ah[1], ah[2], ah[3]);
                ldsm4(swz(sbase + AL_OFF, a_row + 16 * m, a_chunk),
                      al[0], al[1], al[2], al[3]);
#pragma unroll
                for (int n = 0; n < 4; n++)   // hh
                    mma16816(acc[n][0], acc[n][1], acc[n][2], acc[n][3],
                             ah[0], ah[1], ah[2], ah[3],
                             bfh[kc][n][0], bfh[kc][n][1]);
#pragma unroll
                for (int n = 0; n < 4; n++)   // hl
                    mma16816(acc[n][0], acc[n][1], acc[n][2], acc[n][3],
                             ah[0], ah[1], ah[2], ah[3],
                             bfl[kc][n][0], bfl[kc][n][1]);
#pragma unroll
                for (int n = 0; n < 4; n++)   // lh
                    mma16816(acc[n][0], acc[n][1], acc[n][2], acc[n][3],
                             al[0], al[1], al[2], al[3],
                             bfh[kc][n][0], bfh[kc][n][1]);
            }

            // all smem reads of this tile done after last m-block's ldsm
            if (m == 3) mbar_arrive(read_cur);

            // epilogue for this m-block (regs + global only)
            const int grow = row0 + m_base + 16 * m + group;
            const float xn0 = __ldg(&g_xn[grow]);
            const float xn1 = __ldg(&g_xn[grow + 8]);
            const size_t gr0 = (size_t)grow * NN;
            const size_t gr1 = gr0 + (size_t)8 * NN;
#pragma unroll
            for (int n = 0; n < 4; n++) {
                const int gcol = col0 + n_base + 8 * n + 2 * tig;
                float e0 = ex2f(fminf(fmaf(TWO_LOG2E, acc[n][0], -(xn0 + ynv[n][0])), 0.f));
                float e1 = ex2f(fminf(fmaf(TWO_LOG2E, acc[n][1], -(xn0 + ynv[n][1])), 0.f));
                float e2 = ex2f(fminf(fmaf(TWO_LOG2E, acc[n][2], -(xn1 + ynv[n][0])), 0.f));
                float e3 = ex2f(fminf(fmaf(TWO_LOG2E, acc[n][3], -(xn1 + ynv[n][1])), 0.f));
                __stcs(reinterpret_cast<float2*>(out + gr0 + gcol), make_float2(e0, e1));
                __stcs(reinterpret_cast<float2*>(out + gr1 + gcol), make_float2(e2, e3));
            }
        }
    }
}

// ---------------------------------------------------------------------------
extern "C" void kernel_launch(void* const* d_in, const int* in_sizes, int n_in,
                              void* d_out, int out_size) {
    const float* x = (const float*)d_in[0];
    const float* y = (const float*)d_in[1];
    float* out = (float*)d_out;
    (void)in_sizes; (void)n_in; (void)out_size;

    cudaFuncSetAttribute(rbf_mma_kernel,
                         cudaFuncAttributeMaxDynamicSharedMemorySize,
                         SMEM_DYN_BYTES);

    presplit_kernel<<<(NN * DD / 4) / 256, 256>>>(x, y);
    rbf_mma_kernel<<<NCTA, 256, SMEM_DYN_BYTES>>>(out);
}

// round 9
// speedup vs baseline: 1.1903x; 1.1903x over previous
#include <cuda_runtime.h>
#include <cuda_bf16.h>
#include <cstdint>

// RBF: out[i][j] = exp(-||x_i - y_j||^2), N=M=8192, D=64, fp32.
// dist2 = xn + yn - 2*dot; dot via bf16 hi/lo split on mma.sync (HMMA).
// Round 9: R7 mbarrier pipeline, but ONE 512-thread CTA per SM with a
// 256(M)x128(N) tile: A resident 64KB, B double-buffered. Halves global B
// re-reads (128-row strips -> 256-row strips) and widens the barrier domain.

#define NN 8192
#define DD 64
#define TILE_M 256
#define TILE_N 128
#define NSM 148
#define NCTA NSM                 // 148, 1 CTA/SM
#define NTHREADS 512
#define TOTTILES ((NN / TILE_M) * (NN / TILE_N))   // 32*64 = 2048

// smem layout (dynamic): A resident (64KB), B double-buffered (2x32KB)
#define AH_OFF 0
#define AL_OFF 32768
#define BH_OFF(buf) (65536 + (buf) * 32768)
#define BL_OFF(buf) (65536 + (buf) * 32768 + 16384)
#define SMEM_DYN_BYTES 131072

#define LOG2E      1.4426950408889634f
#define TWO_LOG2E  2.8853900817779268f

__device__ float g_xn[NN];   // ||x_i||^2 * log2(e)
__device__ float g_yn[NN];   // ||y_j||^2 * log2(e)
__device__ __nv_bfloat16 g_xh[NN * DD];
__device__ __nv_bfloat16 g_xl[NN * DD];
__device__ __nv_bfloat16 g_yh[NN * DD];
__device__ __nv_bfloat16 g_yl[NN * DD];

// ------------------------- helpers -----------------------------------------
__device__ __forceinline__ uint32_t smem_u32(const void* p) {
    uint32_t a;
    asm("{ .reg .u64 t; cvta.to.shared.u64 t, %1; cvt.u32.u64 %0, t; }"
        : "=r"(a) : "l"(p));
    return a;
}

__device__ __forceinline__ void cp_async16(uint32_t saddr, const void* gaddr) {
    asm volatile("cp.async.cg.shared.global [%0], [%1], 16;"
                 :: "r"(saddr), "l"(gaddr) : "memory");
}

__device__ __forceinline__ void mbar_init(uint32_t addr, uint32_t cnt) {
    asm volatile("mbarrier.init.shared.b64 [%0], %1;"
                 :: "r"(addr), "r"(cnt) : "memory");
}

__device__ __forceinline__ void cp_arrive_noinc(uint32_t addr) {
    asm volatile("cp.async.mbarrier.arrive.noinc.shared.b64 [%0];"
                 :: "r"(addr) : "memory");
}

__device__ __forceinline__ void mbar_arrive(uint32_t addr) {
    asm volatile("{ .reg .b64 tk; mbarrier.arrive.shared.b64 tk, [%0]; }"
                 :: "r"(addr) : "memory");
}

__device__ __forceinline__ void mbar_wait(uint32_t addr, uint32_t parity) {
    asm volatile(
        "{\n\t.reg .pred P1;\n\t"
        "WL_%=:\n\t"
        "mbarrier.try_wait.parity.acquire.cta.shared::cta.b64 P1, [%0], %1, 0x989680;\n\t"
        "@P1 bra.uni WD_%=;\n\t"
        "bra.uni WL_%=;\n\t"
        "WD_%=:\n\t}"
        :: "r"(addr), "r"(parity) : "memory");
}

__device__ __forceinline__ void ldsm4(uint32_t addr, uint32_t& r0, uint32_t& r1,
                                      uint32_t& r2, uint32_t& r3) {
    asm volatile("ldmatrix.sync.aligned.m8n8.x4.shared.b16 {%0,%1,%2,%3}, [%4];"
                 : "=r"(r0), "=r"(r1), "=r"(r2), "=r"(r3) : "r"(addr));
}

__device__ __forceinline__ void mma16816(float& c0, float& c1, float& c2, float& c3,
                                         uint32_t a0, uint32_t a1, uint32_t a2,
                                         uint32_t a3, uint32_t b0, uint32_t b1) {
    asm volatile(
        "mma.sync.aligned.m16n8k16.row.col.f32.bf16.bf16.f32 "
        "{%0,%1,%2,%3}, {%4,%5,%6,%7}, {%8,%9}, {%0,%1,%2,%3};"
        : "+f"(c0), "+f"(c1), "+f"(c2), "+f"(c3)
        : "r"(a0), "r"(a1), "r"(a2), "r"(a3), "r"(b0), "r"(b1));
}

__device__ __forceinline__ float ex2f(float v) {
    float r;
    asm("ex2.approx.ftz.f32 %0, %1;" : "=f"(r) : "f"(v));
    return r;
}

__device__ __forceinline__ uint32_t swz(uint32_t base, int row, int chunk) {
    return base + row * 128 + (((unsigned)chunk ^ ((unsigned)row & 7u)) << 4);
}

__device__ __forceinline__ void split2(float v0, float v1,
                                       uint32_t& hp, uint32_t& lp) {
    __nv_bfloat16 h0 = __float2bfloat16(v0);
    __nv_bfloat16 h1 = __float2bfloat16(v1);
    __nv_bfloat16 l0 = __float2bfloat16(v0 - __bfloat162float(h0));
    __nv_bfloat16 l1 = __float2bfloat16(v1 - __bfloat162float(h1));
    __nv_bfloat162 hh(h0, h1), ll(l0, l1);
    hp = *reinterpret_cast<uint32_t*>(&hh);
    lp = *reinterpret_cast<uint32_t*>(&ll);
}

// ---------------------------------------------------------------------------
__global__ void presplit_kernel(const float* __restrict__ x,
                                const float* __restrict__ y) {
    int tid = blockIdx.x * blockDim.x + threadIdx.x;
    int row = tid >> 4;
    int q = tid & 15;

    float4 vx = __ldg(reinterpret_cast<const float4*>(x + (size_t)row * DD) + q);
    float4 vy = __ldg(reinterpret_cast<const float4*>(y + (size_t)row * DD) + q);

    uint32_t h0, l0, h1, l1;
    split2(vx.x, vx.y, h0, l0);
    split2(vx.z, vx.w, h1, l1);
    *reinterpret_cast<uint2*>(&g_xh[(size_t)row * DD + q * 4]) = make_uint2(h0, h1);
    *reinterpret_cast<uint2*>(&g_xl[(size_t)row * DD + q * 4]) = make_uint2(l0, l1);
    split2(vy.x, vy.y, h0, l0);
    split2(vy.z, vy.w, h1, l1);
    *reinterpret_cast<uint2*>(&g_yh[(size_t)row * DD + q * 4]) = make_uint2(h0, h1);
    *reinterpret_cast<uint2*>(&g_yl[(size_t)row * DD + q * 4]) = make_uint2(l0, l1);

    float sx = vx.x * vx.x + vx.y * vx.y + vx.z * vx.z + vx.w * vx.w;
    float sy = vy.x * vy.x + vy.y * vy.y + vy.z * vy.z + vy.w * vy.w;
#pragma unroll
    for (int o = 8; o >= 1; o >>= 1) {
        sx += __shfl_xor_sync(0xffffffffu, sx, o, 16);
        sy += __shfl_xor_sync(0xffffffffu, sy, o, 16);
    }
    if (q == 0) {
        g_xn[row] = sx * LOG2E;
        g_yn[row] = sy * LOG2E;
    }
}

// ---------------------------------------------------------------------------
// tile fills (all 512 threads)
__device__ __forceinline__ void load_A(uint32_t sbase, int t, int row0) {
    const __nv_bfloat16* sh = g_xh + (size_t)row0 * DD;
    const __nv_bfloat16* sl = g_xl + (size_t)row0 * DD;
#pragma unroll
    for (int it = 0; it < 4; it++) {
        int idx = t + NTHREADS * it;   // 0..2047
        int r = idx >> 3;              // row 0..255
        int q = idx & 7;
        cp_async16(swz(sbase + AH_OFF, r, q), sh + (size_t)r * DD + q * 8);
        cp_async16(swz(sbase + AL_OFF, r, q), sl + (size_t)r * DD + q * 8);
    }
}

__device__ __forceinline__ void load_B(uint32_t sbase, int buf, int t, int col0) {
    const __nv_bfloat16* sh = g_yh + (size_t)col0 * DD;
    const __nv_bfloat16* sl = g_yl + (size_t)col0 * DD;
    const uint32_t bh = sbase + BH_OFF(buf);
    const uint32_t bl = sbase + BL_OFF(buf);
#pragma unroll
    for (int it = 0; it < 2; it++) {
        int idx = t + NTHREADS * it;   // 0..1023
        int r = idx >> 3;              // row 0..127
        int q = idx & 7;
        cp_async16(swz(bh, r, q), sh + (size_t)r * DD + q * 8);
        cp_async16(swz(bl, r, q), sl + (size_t)r * DD + q * 8);
    }
}

// ---------------------------------------------------------------------------
// Persistent kernel, 512 threads (16 warps: 4x4), grid = 148 (1/SM).
// ---------------------------------------------------------------------------
__global__ __launch_bounds__(NTHREADS, 1)
void rbf_mma_kernel(float* __restrict__ out) {
    extern __shared__ __align__(128) char smem_raw[];
    const uint32_t sbase = smem_u32(smem_raw);

    __shared__ __align__(8) uint64_t s_mbar[4];  // fill0, fill1, read0, read1

    const int t    = threadIdx.x;
    const int wid  = t >> 5;
    const int lane = t & 31;
    const int b    = blockIdx.x;

    const uint32_t fill_a0 = smem_u32(&s_mbar[0]);
    const uint32_t fill_a1 = smem_u32(&s_mbar[1]);
    const uint32_t read_a0 = smem_u32(&s_mbar[2]);
    const uint32_t read_a1 = smem_u32(&s_mbar[3]);

    if (t == 0) {
        mbar_init(fill_a0, NTHREADS);
        mbar_init(fill_a1, NTHREADS);
        mbar_init(read_a0, NTHREADS);
        mbar_init(read_a1, NTHREADS);
    }
    __syncthreads();

    // static tile schedule: contiguous row-major runs over 2048 tiles
    const int base  = TOTTILES / NCTA;           // 13
    const int rem   = TOTTILES % NCTA;           // 124
    const int cnt   = base + (b < rem);
    const int start = (b < rem) ? (base + 1) * b : rem * (base + 1) + base * (b - rem);

    // warp tiling: 4x4 warps, warp tile 64(M)x32(N)
    const int warp_row = wid >> 2;               // 0..3
    const int warp_col = wid & 3;                // 0..3
    const int m_base = warp_row * 64;            // A row base (0..192)
    const int n_base = warp_col * 32;            // B row base (0..96)
    const int a_row = m_base + (lane & 15);
    const int a_half = lane >> 4;
    const int b_row = n_base + ((lane >> 4) & 1) * 8 + (lane & 7);
    const int b_half = (lane >> 3) & 1;
    const int group = lane >> 2;
    const int tig   = lane & 3;

    // prologue
    load_A(sbase, t, (start >> 6) * TILE_M);
    load_B(sbase, 0, t, (start & 63) * TILE_N);
    cp_arrive_noinc(fill_a0);

    float xnv[4][2];   // persistent per row strip

    for (int s = 0; s < cnt; s++) {
        const int id   = start + s;
        const int ti   = id >> 6;
        const int tj   = id & 63;
        const int row0 = ti * TILE_M;
        const int col0 = tj * TILE_N;
        const int buf  = s & 1;
        const uint32_t fill_cur = buf ? fill_a1 : fill_a0;
        const uint32_t fill_nxt = buf ? fill_a0 : fill_a1;
        const uint32_t read_cur = buf ? read_a1 : read_a0;
        const uint32_t read_oth = buf ? read_a0 : read_a1;

        // 1. all threads done reading buf^1 (mainloop s-1)
        if (s > 0) mbar_wait(read_oth, ((s - 1) >> 1) & 1);

        const bool strip_entry = (s == 0) || (((id - 1) >> 6) != ti);

        // 2. deferred A+B load at row-strip change
        if (s > 0 && strip_entry) {
            load_A(sbase, t, row0);
            load_B(sbase, buf, t, col0);
            cp_arrive_noinc(fill_cur);
        }
        // 3. prefetch next B if same row strip
        if (s + 1 < cnt && (((id + 1) >> 6) == ti)) {
            load_B(sbase, buf ^ 1, t, ((id + 1) & 63) * TILE_N);
            cp_arrive_noinc(fill_nxt);
        }

        // row-strip norms (persistent registers)
        if (strip_entry) {
#pragma unroll
            for (int m = 0; m < 4; m++) {
                xnv[m][0] = __ldg(&g_xn[row0 + m_base + 16 * m + group]);
                xnv[m][1] = __ldg(&g_xn[row0 + m_base + 16 * m + group + 8]);
            }
        }
        float ynv[4][2];
#pragma unroll
        for (int n = 0; n < 4; n++) {
            ynv[n][0] = __ldg(&g_yn[col0 + n_base + 8 * n + 2 * tig]);
            ynv[n][1] = __ldg(&g_yn[col0 + n_base + 8 * n + 2 * tig + 1]);
        }

        // 4. wait B(s) data ready
        mbar_wait(fill_cur, (s >> 1) & 1);

        // ---- mainloop (identical to R7 per-warp structure) ----
        const uint32_t bhb = sbase + BH_OFF(buf);
        const uint32_t blb = sbase + BL_OFF(buf);

        float acc[4][4][4];
#pragma unroll
        for (int m = 0; m < 4; m++)
#pragma unroll
            for (int n = 0; n < 4; n++)
#pragma unroll
                for (int e = 0; e < 4; e++) acc[m][n][e] = 0.f;

#pragma unroll
        for (int kc = 0; kc < 4; kc++) {
            const int a_chunk = kc * 2 + a_half;
            const int b_chunk = kc * 2 + b_half;

            uint32_t ah[4][4];
#pragma unroll
            for (int m = 0; m < 4; m++)
                ldsm4(swz(sbase + AH_OFF, a_row + 16 * m, a_chunk),
                      ah[m][0], ah[m][1], ah[m][2], ah[m][3]);
            uint32_t bh[4][2];
#pragma unroll
            for (int p = 0; p < 2; p++)
                ldsm4(swz(bhb, b_row + 16 * p, b_chunk),
                      bh[2 * p][0], bh[2 * p][1], bh[2 * p + 1][0], bh[2 * p + 1][1]);
#pragma unroll
            for (int m = 0; m < 4; m++)
#pragma unroll
                for (int n = 0; n < 4; n++)
                    mma16816(acc[m][n][0], acc[m][n][1], acc[m][n][2], acc[m][n][3],
                             ah[m][0], ah[m][1], ah[m][2], ah[m][3],
                             bh[n][0], bh[n][1]);

            uint32_t bl[4][2];
#pragma unroll
            for (int p = 0; p < 2; p++)
                ldsm4(swz(blb, b_row + 16 * p, b_chunk),
                      bl[2 * p][0], bl[2 * p][1], bl[2 * p + 1][0], bl[2 * p + 1][1]);
#pragma unroll
            for (int m = 0; m < 4; m++)
#pragma unroll
                for (int n = 0; n < 4; n++)
                    mma16816(acc[m][n][0], acc[m][n][1], acc[m][n][2], acc[m][n][3],
                             ah[m][0], ah[m][1], ah[m][2], ah[m][3],
                             bl[n][0], bl[n][1]);

            uint32_t al[4][4];
#pragma unroll
            for (int m = 0; m < 4; m++)
                ldsm4(swz(sbase + AL_OFF, a_row + 16 * m, a_chunk),
                      al[m][0], al[m][1], al[m][2], al[m][3]);
#pragma unroll
            for (int m = 0; m < 4; m++)
#pragma unroll
                for (int n = 0; n < 4; n++)
                    mma16816(acc[m][n][0], acc[m][n][1], acc[m][n][2], acc[m][n][3],
                             al[m][0], al[m][1], al[m][2], al[m][3],
                             bh[n][0], bh[n][1]);
        }

        // 5. this thread done reading smem tiles
        mbar_arrive(read_cur);

        // ---- epilogue (regs + global only; unclamped: exp(+eps) ~ 1) ----
#pragma unroll
        for (int m = 0; m < 4; m++) {
            const size_t grow0 = (size_t)(row0 + m_base + 16 * m + group) * NN;
            const size_t grow1 = grow0 + (size_t)8 * NN;
#pragma unroll
            for (int n = 0; n < 4; n++) {
                const int gcol = col0 + n_base + 8 * n + 2 * tig;
                float e0 = ex2f(fmaf(TWO_LOG2E, acc[m][n][0], -(xnv[m][0] + ynv[n][0])));
                float e1 = ex2f(fmaf(TWO_LOG2E, acc[m][n][1], -(xnv[m][0] + ynv[n][1])));
                float e2 = ex2f(fmaf(TWO_LOG2E, acc[m][n][2], -(xnv[m][1] + ynv[n][0])));
                float e3 = ex2f(fmaf(TWO_LOG2E, acc[m][n][3], -(xnv[m][1] + ynv[n][1])));
                __stcs(reinterpret_cast<float2*>(out + grow0 + gcol), make_float2(e0, e1));
                __stcs(reinterpret_cast<float2*>(out + grow1 + gcol), make_float2(e2, e3));
            }
        }
    }
}

// ---------------------------------------------------------------------------
extern "C" void kernel_launch(void* const* d_in, const int* in_sizes, int n_in,
                              void* d_out, int out_size) {
    const float* x = (const float*)d_in[0];
    const float* y = (const float*)d_in[1];
    float* out = (float*)d_out;
    (void)in_sizes; (void)n_in; (void)out_size;

    cudaFuncSetAttribute(rbf_mma_kernel,
                         cudaFuncAttributeMaxDynamicSharedMemorySize,
                         SMEM_DYN_BYTES);

    presplit_kernel<<<(NN * DD / 4) / 256, 256>>>(x, y);
    rbf_mma_kernel<<<NCTA, NTHREADS, SMEM_DYN_BYTES>>>(out);
}